// round 3
// baseline (speedup 1.0000x reference)
#include <cuda_runtime.h>

#define NPTS   65536     // B*T
#define TPB    256
#define PPB    (TPB/4)   // 64 points per block, 4 lanes per point

typedef unsigned long long u64;

__device__ __forceinline__ u64 pk2(float a, float b) {
    u64 r; asm("mov.b64 %0, {%1,%2};" : "=l"(r) : "f"(a), "f"(b)); return r;
}
__device__ __forceinline__ u64 dup2(float a) { return pk2(a, a); }
__device__ __forceinline__ void upk2(u64 v, float& a, float& b) {
    asm("mov.b64 {%0,%1}, %2;" : "=f"(a), "=f"(b) : "l"(v));
}
__device__ __forceinline__ void fma2(u64& d, u64 a, u64 b) {
    asm("fma.rn.f32x2 %0, %1, %2, %0;" : "+l"(d) : "l"(a), "l"(b));
}

__global__ __launch_bounds__(TPB, 4)
void decoder_fused_kernel(
    const float* __restrict__ p,      // [16,4096,3]
    const float* __restrict__ c,      // [16,4,128,128,32]
    const float* __restrict__ Cmat,   // [16,4,4,3]
    const float* __restrict__ fcpW,   // [3,32]
    const float* __restrict__ fcpb,   // [32]
    const float* __restrict__ W0,     // [5,32,32]
    const float* __restrict__ b0,     // [5,32]
    const float* __restrict__ W1,     // [5,32,32]
    const float* __restrict__ b1,     // [5,32]
    const float* __restrict__ Wout,   // [32,1]
    const float* __restrict__ bout,   // [1]
    float* __restrict__ out)          // [16,4096]
{
    __shared__ __align__(16) float sW0[5 * 1024];
    __shared__ __align__(16) float sW1[5 * 1024];
    __shared__ __align__(16) float sb0[5 * 32];
    __shared__ __align__(16) float sb1[5 * 32];
    __shared__ __align__(16) float sWp[96];
    __shared__ __align__(16) float sbp[32];
    __shared__ __align__(16) float sWo[32];
    __shared__ float sbo;
    __shared__ float sC[4][8];   // per view: c00,c01,c02,c10,c11,c12,den

    const int tid = threadIdx.x;
    const int q4  = tid & 3;                      // channel quarter: owns ch [q4*8, q4*8+8)
    const int pt  = blockIdx.x * PPB + (tid >> 2);
    const int b   = pt >> 12;                     // 4096 pts per batch; block never spans two b

    // ---- stage weights in shared ----
    for (int i = tid; i < 5120; i += TPB) { sW0[i] = W0[i]; sW1[i] = W1[i]; }
    if (tid < 160) { sb0[tid] = b0[tid]; sb1[tid] = b1[tid]; }
    if (tid < 96) sWp[tid] = fcpW[tid];
    if (tid < 32) { sbp[tid] = fcpb[tid]; sWo[tid] = Wout[tid]; }
    if (tid == 0) sbo = bout[0];
    if (tid < 28) {
        int l = tid / 7, k = tid % 7;
        const float* Cb = Cmat + (b * 4 + l) * 12;   // [4,3] per (b,l)
        sC[l][k] = (k < 6) ? Cb[k] : (Cb[9] + 0.05f);
    }
    __syncthreads();

    // ---- load point (4 lanes redundantly; L1 broadcast) ----
    const float pr0 = p[pt * 3 + 0];
    const float pr1 = p[pt * 3 + 1];
    const float pr2 = p[pt * 3 + 2];
    const float ps0 = pr0 / 0.55f;
    const float ps1 = pr1 / 0.55f;
    const float ps2 = pr2 / 0.55f;

    // ---- bilinear gather over 4 views -> packed cf (this lane's 8 channels) ----
    u64 cf2[4];
    #pragma unroll
    for (int m = 0; m < 4; m++) cf2[m] = 0ull;

    const float interval = 2.0f / 127.0f;

    #pragma unroll
    for (int l = 0; l < 4; l++) {
        const float c00 = sC[l][0], c01 = sC[l][1], c02 = sC[l][2];
        const float c10 = sC[l][3], c11 = sC[l][4], c12 = sC[l][5];
        const float den = sC[l][6];

        float px = (c00 * ps0 + c01 * ps1 + c02 * ps2) / den;
        float py = (c10 * ps0 + c11 * ps1 + c12 * ps2) / den;

        float xg = (px + 1.0f) / interval;
        float yg = (py + 1.0f) / interval;
        // match ref: first >=127 -> 126.9, then <0 -> 0
        xg = (xg >= 127.0f) ? 126.9f : xg;  xg = (xg < 0.0f) ? 0.0f : xg;
        yg = (yg >= 127.0f) ? 126.9f : yg;  yg = (yg < 0.0f) ? 0.0f : yg;

        // half-to-even rounding, same as jnp.round
        const float xl = rintf(xg - 0.5f), xr = rintf(xg + 0.5f);
        const float yl = rintf(yg - 0.5f), yh = rintf(yg + 0.5f);
        const int xil = (int)xl, xir = (int)xr;
        const int yil = (int)yl, yih = (int)yh;

        const float dx = xr - xg, dy = yh - yg;
        const u64 W11 = dup2(dx * dy);
        const u64 W12 = dup2((1.0f - dx) * dy);
        const u64 W21 = dup2(dx * (1.0f - dy));
        const u64 W22 = dup2((1.0f - dx) * (1.0f - dy));

        const int base = (b * 4 + l) * 128 * 128;     // plane row index
        // 4 lanes of a point cover contiguous 4x32B of the same 128B corner row
        const ulonglong2* r11 = (const ulonglong2*)(c + (size_t)(base + xil * 128 + yil) * 32) + q4 * 2;
        const ulonglong2* r12 = (const ulonglong2*)(c + (size_t)(base + xir * 128 + yil) * 32) + q4 * 2;
        const ulonglong2* r21 = (const ulonglong2*)(c + (size_t)(base + xil * 128 + yih) * 32) + q4 * 2;
        const ulonglong2* r22 = (const ulonglong2*)(c + (size_t)(base + xir * 128 + yih) * 32) + q4 * 2;

        #pragma unroll
        for (int q = 0; q < 2; q++) {
            const ulonglong2 a = r11[q];
            const ulonglong2 e = r12[q];
            const ulonglong2 f = r21[q];
            const ulonglong2 g = r22[q];
            fma2(cf2[2*q    ], W11, a.x);  fma2(cf2[2*q + 1], W11, a.y);
            fma2(cf2[2*q    ], W12, e.x);  fma2(cf2[2*q + 1], W12, e.y);
            fma2(cf2[2*q    ], W21, f.x);  fma2(cf2[2*q + 1], W21, f.y);
            fma2(cf2[2*q    ], W22, g.x);  fma2(cf2[2*q + 1], W22, g.y);
        }
    }

    float cf[8];
    #pragma unroll
    for (int m = 0; m < 4; m++) upk2(cf2[m], cf[2*m], cf[2*m + 1]);

    // ---- fc_p + first cf add (this lane's 8 output channels) ----
    const int chb = q4 * 8;
    float x[8];
    #pragma unroll
    for (int j = 0; j < 8; j++) {
        const int ch = chb + j;
        float v = sbp[ch];
        v = fmaf(pr0, sWp[ch],      v);
        v = fmaf(pr1, sWp[32 + ch], v);
        v = fmaf(pr2, sWp[64 + ch], v);
        x[j] = v + cf[j];
    }

    const unsigned FULL = 0xffffffffu;

    // ---- 5 resnet blocks ----
    #pragma unroll 1
    for (int blk = 0; blk < 5; blk++) {
        if (blk > 0) {
            #pragma unroll
            for (int j = 0; j < 8; j++) x[j] += cf[j];
        }
        const float* w0base = sW0 + blk * 1024 + chb;  // column slice for this lane
        const float* w1base = sW1 + blk * 1024 + chb;

        // ---- h = relu(x) @ W0 + b0 (packed accumulation) ----
        u64 acc2[4];
        {
            const ulonglong2* bb = (const ulonglong2*)(sb0 + blk * 32 + chb);
            const ulonglong2 b01 = bb[0], b23 = bb[1];
            acc2[0] = b01.x; acc2[1] = b01.y; acc2[2] = b23.x; acc2[3] = b23.y;
        }
        #pragma unroll
        for (int kk = 0; kk < 8; kk++) {
            const u64 vv0 = dup2(fmaxf(__shfl_sync(FULL, x[kk], 0, 4), 0.0f));
            const u64 vv1 = dup2(fmaxf(__shfl_sync(FULL, x[kk], 1, 4), 0.0f));
            const u64 vv2 = dup2(fmaxf(__shfl_sync(FULL, x[kk], 2, 4), 0.0f));
            const u64 vv3 = dup2(fmaxf(__shfl_sync(FULL, x[kk], 3, 4), 0.0f));

            const ulonglong2* r0 = (const ulonglong2*)(w0base + (kk     ) * 32);
            const ulonglong2* r1 = (const ulonglong2*)(w0base + (kk +  8) * 32);
            const ulonglong2* r2 = (const ulonglong2*)(w0base + (kk + 16) * 32);
            const ulonglong2* r3 = (const ulonglong2*)(w0base + (kk + 24) * 32);
            #pragma unroll
            for (int q = 0; q < 2; q++) {
                const ulonglong2 a = r0[q], e = r1[q], f = r2[q], g = r3[q];
                fma2(acc2[2*q    ], vv0, a.x);  fma2(acc2[2*q + 1], vv0, a.y);
                fma2(acc2[2*q    ], vv1, e.x);  fma2(acc2[2*q + 1], vv1, e.y);
                fma2(acc2[2*q    ], vv2, f.x);  fma2(acc2[2*q + 1], vv2, f.y);
                fma2(acc2[2*q    ], vv3, g.x);  fma2(acc2[2*q + 1], vv3, g.y);
            }
        }
        float h[8];
        #pragma unroll
        for (int m = 0; m < 4; m++) upk2(acc2[m], h[2*m], h[2*m + 1]);

        // ---- x += relu(h) @ W1 + b1 (packed accumulation) ----
        {
            const ulonglong2* bb = (const ulonglong2*)(sb1 + blk * 32 + chb);
            const ulonglong2 b01 = bb[0], b23 = bb[1];
            acc2[0] = b01.x; acc2[1] = b01.y; acc2[2] = b23.x; acc2[3] = b23.y;
        }
        #pragma unroll
        for (int kk = 0; kk < 8; kk++) {
            const u64 vv0 = dup2(fmaxf(__shfl_sync(FULL, h[kk], 0, 4), 0.0f));
            const u64 vv1 = dup2(fmaxf(__shfl_sync(FULL, h[kk], 1, 4), 0.0f));
            const u64 vv2 = dup2(fmaxf(__shfl_sync(FULL, h[kk], 2, 4), 0.0f));
            const u64 vv3 = dup2(fmaxf(__shfl_sync(FULL, h[kk], 3, 4), 0.0f));

            const ulonglong2* r0 = (const ulonglong2*)(w1base + (kk     ) * 32);
            const ulonglong2* r1 = (const ulonglong2*)(w1base + (kk +  8) * 32);
            const ulonglong2* r2 = (const ulonglong2*)(w1base + (kk + 16) * 32);
            const ulonglong2* r3 = (const ulonglong2*)(w1base + (kk + 24) * 32);
            #pragma unroll
            for (int q = 0; q < 2; q++) {
                const ulonglong2 a = r0[q], e = r1[q], f = r2[q], g = r3[q];
                fma2(acc2[2*q    ], vv0, a.x);  fma2(acc2[2*q + 1], vv0, a.y);
                fma2(acc2[2*q    ], vv1, e.x);  fma2(acc2[2*q + 1], vv1, e.y);
                fma2(acc2[2*q    ], vv2, f.x);  fma2(acc2[2*q + 1], vv2, f.y);
                fma2(acc2[2*q    ], vv3, g.x);  fma2(acc2[2*q + 1], vv3, g.y);
            }
        }
        #pragma unroll
        for (int m = 0; m < 4; m++) {
            float d0, d1; upk2(acc2[m], d0, d1);
            x[2*m]     += d0;
            x[2*m + 1] += d1;
        }
    }

    // ---- output head: partial dot over this lane's 8 channels, reduce over 4 lanes ----
    float acc = 0.0f;
    #pragma unroll
    for (int j = 0; j < 8; j++)
        acc = fmaf(fmaxf(x[j], 0.0f), sWo[chb + j], acc);
    acc += __shfl_xor_sync(FULL, acc, 1);
    acc += __shfl_xor_sync(FULL, acc, 2);
    if (q4 == 0) out[pt] = acc + sbo;
}

extern "C" void kernel_launch(void* const* d_in, const int* in_sizes, int n_in,
                              void* d_out, int out_size)
{
    // metadata order: p, z, c, C_mat, fc_p_W, fc_p_b,
    //                 blocks_W0, blocks_b0, blocks_W1, blocks_b1, fc_out_W, fc_out_b
    const float* p    = (const float*)d_in[0];
    // d_in[1] = z (unused by the reference graph)
    const float* c    = (const float*)d_in[2];
    const float* Cm   = (const float*)d_in[3];
    const float* fpW  = (const float*)d_in[4];
    const float* fpb  = (const float*)d_in[5];
    const float* W0   = (const float*)d_in[6];
    const float* b0   = (const float*)d_in[7];
    const float* W1   = (const float*)d_in[8];
    const float* b1   = (const float*)d_in[9];
    const float* Wo   = (const float*)d_in[10];
    const float* bo   = (const float*)d_in[11];
    float* out = (float*)d_out;

    decoder_fused_kernel<<<NPTS / PPB, TPB>>>(p, c, Cm, fpW, fpb, W0, b0, W1, b1, Wo, bo, out);
}

// round 4
// speedup vs baseline: 1.3653x; 1.3653x over previous
#include <cuda_runtime.h>

#define NPTS   65536     // B*T
#define TPB    256
#define PPB    128       // points per block: 64 groups x 2 points per thread

typedef unsigned long long u64;

__device__ __forceinline__ u64 pk2(float a, float b) {
    u64 r; asm("mov.b64 %0, {%1,%2};" : "=l"(r) : "f"(a), "f"(b)); return r;
}
__device__ __forceinline__ u64 dup2(float a) { return pk2(a, a); }
__device__ __forceinline__ void upk2(u64 v, float& a, float& b) {
    asm("mov.b64 {%0,%1}, %2;" : "=f"(a), "=f"(b) : "l"(v));
}
__device__ __forceinline__ void fma2(u64& d, u64 a, u64 b) {
    asm("fma.rn.f32x2 %0, %1, %2, %0;" : "+l"(d) : "l"(a), "l"(b));
}

__global__ __launch_bounds__(TPB, 2)
void decoder_fused_kernel(
    const float* __restrict__ p,      // [16,4096,3]
    const float* __restrict__ c,      // [16,4,128,128,32]
    const float* __restrict__ Cmat,   // [16,4,4,3]
    const float* __restrict__ fcpW,   // [3,32]
    const float* __restrict__ fcpb,   // [32]
    const float* __restrict__ W0,     // [5,32,32]
    const float* __restrict__ b0,     // [5,32]
    const float* __restrict__ W1,     // [5,32,32]
    const float* __restrict__ b1,     // [5,32]
    const float* __restrict__ Wout,   // [32,1]
    const float* __restrict__ bout,   // [1]
    float* __restrict__ out)          // [16,4096]
{
    __shared__ __align__(16) float sW0[5 * 1024];
    __shared__ __align__(16) float sW1[5 * 1024];
    __shared__ __align__(16) float sb0[5 * 32];
    __shared__ __align__(16) float sb1[5 * 32];
    __shared__ __align__(16) float sWp[96];
    __shared__ __align__(16) float sbp[32];
    __shared__ __align__(16) float sWo[32];
    __shared__ float sbo;
    __shared__ float sC[4][8];   // per view: c00,c01,c02,c10,c11,c12,den

    const int tid = threadIdx.x;
    const int q4  = tid & 3;                      // channel quarter: owns ch [q4*8, q4*8+8)
    const int g   = tid >> 2;                     // group id 0..63
    const int pt0 = blockIdx.x * PPB + g;         // point A
    const int pt1 = pt0 + 64;                     // point B (same batch: PPB=128 divides 4096)
    const int b   = pt0 >> 12;

    // ---- stage weights in shared ----
    for (int i = tid; i < 5120; i += TPB) { sW0[i] = W0[i]; sW1[i] = W1[i]; }
    if (tid < 160) { sb0[tid] = b0[tid]; sb1[tid] = b1[tid]; }
    if (tid < 96) sWp[tid] = fcpW[tid];
    if (tid < 32) { sbp[tid] = fcpb[tid]; sWo[tid] = Wout[tid]; }
    if (tid == 0) sbo = bout[0];
    if (tid < 28) {
        int l = tid / 7, k = tid % 7;
        const float* Cb = Cmat + (b * 4 + l) * 12;
        sC[l][k] = (k < 6) ? Cb[k] : (Cb[9] + 0.05f);
    }
    __syncthreads();

    const float interval = 2.0f / 127.0f;
    const unsigned FULL = 0xffffffffu;
    const int chb = q4 * 8;

    // per-point state
    float cf[2][8];
    float x[2][8];
    float pr[2][3];

    #pragma unroll
    for (int pp = 0; pp < 2; pp++) {
        const int pt = pp ? pt1 : pt0;
        const float p0 = p[pt * 3 + 0];
        const float p1 = p[pt * 3 + 1];
        const float p2 = p[pt * 3 + 2];
        pr[pp][0] = p0; pr[pp][1] = p1; pr[pp][2] = p2;
        const float ps0 = p0 / 0.55f;
        const float ps1 = p1 / 0.55f;
        const float ps2 = p2 / 0.55f;

        u64 cf2[4];
        #pragma unroll
        for (int m = 0; m < 4; m++) cf2[m] = 0ull;

        #pragma unroll
        for (int l = 0; l < 4; l++) {
            const float c00 = sC[l][0], c01 = sC[l][1], c02 = sC[l][2];
            const float c10 = sC[l][3], c11 = sC[l][4], c12 = sC[l][5];
            const float den = sC[l][6];

            float px = (c00 * ps0 + c01 * ps1 + c02 * ps2) / den;
            float py = (c10 * ps0 + c11 * ps1 + c12 * ps2) / den;

            float xg = (px + 1.0f) / interval;
            float yg = (py + 1.0f) / interval;
            xg = (xg >= 127.0f) ? 126.9f : xg;  xg = (xg < 0.0f) ? 0.0f : xg;
            yg = (yg >= 127.0f) ? 126.9f : yg;  yg = (yg < 0.0f) ? 0.0f : yg;

            const float xl = rintf(xg - 0.5f), xr = rintf(xg + 0.5f);
            const float yl = rintf(yg - 0.5f), yh = rintf(yg + 0.5f);
            const int xil = (int)xl, xir = (int)xr;
            const int yil = (int)yl, yih = (int)yh;

            const float dx = xr - xg, dy = yh - yg;
            const u64 W11 = dup2(dx * dy);
            const u64 W12 = dup2((1.0f - dx) * dy);
            const u64 W21 = dup2(dx * (1.0f - dy));
            const u64 W22 = dup2((1.0f - dx) * (1.0f - dy));

            const int base = (b * 4 + l) * 128 * 128;
            const ulonglong2* r11 = (const ulonglong2*)(c + (size_t)(base + xil * 128 + yil) * 32) + q4 * 2;
            const ulonglong2* r12 = (const ulonglong2*)(c + (size_t)(base + xir * 128 + yil) * 32) + q4 * 2;
            const ulonglong2* r21 = (const ulonglong2*)(c + (size_t)(base + xil * 128 + yih) * 32) + q4 * 2;
            const ulonglong2* r22 = (const ulonglong2*)(c + (size_t)(base + xir * 128 + yih) * 32) + q4 * 2;

            #pragma unroll
            for (int q = 0; q < 2; q++) {
                const ulonglong2 a = r11[q];
                const ulonglong2 e = r12[q];
                const ulonglong2 f = r21[q];
                const ulonglong2 gg = r22[q];
                fma2(cf2[2*q    ], W11, a.x);   fma2(cf2[2*q + 1], W11, a.y);
                fma2(cf2[2*q    ], W12, e.x);   fma2(cf2[2*q + 1], W12, e.y);
                fma2(cf2[2*q    ], W21, f.x);   fma2(cf2[2*q + 1], W21, f.y);
                fma2(cf2[2*q    ], W22, gg.x);  fma2(cf2[2*q + 1], W22, gg.y);
            }
        }
        #pragma unroll
        for (int m = 0; m < 4; m++) upk2(cf2[m], cf[pp][2*m], cf[pp][2*m + 1]);
    }

    // ---- fc_p + first cf add ----
    #pragma unroll
    for (int pp = 0; pp < 2; pp++) {
        #pragma unroll
        for (int j = 0; j < 8; j++) {
            const int ch = chb + j;
            float v = sbp[ch];
            v = fmaf(pr[pp][0], sWp[ch],      v);
            v = fmaf(pr[pp][1], sWp[32 + ch], v);
            v = fmaf(pr[pp][2], sWp[64 + ch], v);
            x[pp][j] = v + cf[pp][j];
        }
    }

    // ---- 5 resnet blocks, both points share each weight load ----
    #pragma unroll 1
    for (int blk = 0; blk < 5; blk++) {
        if (blk > 0) {
            #pragma unroll
            for (int pp = 0; pp < 2; pp++)
                #pragma unroll
                for (int j = 0; j < 8; j++) x[pp][j] += cf[pp][j];
        }
        const float* w0base = sW0 + blk * 1024 + chb;
        const float* w1base = sW1 + blk * 1024 + chb;

        // h = relu(x) @ W0 + b0
        u64 accA[4], accB[4];
        {
            const ulonglong2* bb = (const ulonglong2*)(sb0 + blk * 32 + chb);
            const ulonglong2 b01 = bb[0], b23 = bb[1];
            accA[0] = b01.x; accA[1] = b01.y; accA[2] = b23.x; accA[3] = b23.y;
            accB[0] = b01.x; accB[1] = b01.y; accB[2] = b23.x; accB[3] = b23.y;
        }
        #pragma unroll
        for (int kk = 0; kk < 8; kk++) {
            const float rxA = fmaxf(x[0][kk], 0.0f);
            const float rxB = fmaxf(x[1][kk], 0.0f);
            const u64 a0 = dup2(__shfl_sync(FULL, rxA, 0, 4));
            const u64 a1 = dup2(__shfl_sync(FULL, rxA, 1, 4));
            const u64 a2 = dup2(__shfl_sync(FULL, rxA, 2, 4));
            const u64 a3 = dup2(__shfl_sync(FULL, rxA, 3, 4));
            const u64 c0 = dup2(__shfl_sync(FULL, rxB, 0, 4));
            const u64 c1 = dup2(__shfl_sync(FULL, rxB, 1, 4));
            const u64 c2 = dup2(__shfl_sync(FULL, rxB, 2, 4));
            const u64 c3 = dup2(__shfl_sync(FULL, rxB, 3, 4));

            const ulonglong2* r0 = (const ulonglong2*)(w0base + (kk     ) * 32);
            const ulonglong2* r1 = (const ulonglong2*)(w0base + (kk +  8) * 32);
            const ulonglong2* r2 = (const ulonglong2*)(w0base + (kk + 16) * 32);
            const ulonglong2* r3 = (const ulonglong2*)(w0base + (kk + 24) * 32);
            #pragma unroll
            for (int q = 0; q < 2; q++) {
                const ulonglong2 wa = r0[q], we = r1[q], wf = r2[q], wg = r3[q];
                fma2(accA[2*q], a0, wa.x);  fma2(accA[2*q+1], a0, wa.y);
                fma2(accA[2*q], a1, we.x);  fma2(accA[2*q+1], a1, we.y);
                fma2(accA[2*q], a2, wf.x);  fma2(accA[2*q+1], a2, wf.y);
                fma2(accA[2*q], a3, wg.x);  fma2(accA[2*q+1], a3, wg.y);
                fma2(accB[2*q], c0, wa.x);  fma2(accB[2*q+1], c0, wa.y);
                fma2(accB[2*q], c1, we.x);  fma2(accB[2*q+1], c1, we.y);
                fma2(accB[2*q], c2, wf.x);  fma2(accB[2*q+1], c2, wf.y);
                fma2(accB[2*q], c3, wg.x);  fma2(accB[2*q+1], c3, wg.y);
            }
        }
        float h[2][8];
        #pragma unroll
        for (int m = 0; m < 4; m++) {
            upk2(accA[m], h[0][2*m], h[0][2*m + 1]);
            upk2(accB[m], h[1][2*m], h[1][2*m + 1]);
        }

        // x += relu(h) @ W1 + b1
        {
            const ulonglong2* bb = (const ulonglong2*)(sb1 + blk * 32 + chb);
            const ulonglong2 b01 = bb[0], b23 = bb[1];
            accA[0] = b01.x; accA[1] = b01.y; accA[2] = b23.x; accA[3] = b23.y;
            accB[0] = b01.x; accB[1] = b01.y; accB[2] = b23.x; accB[3] = b23.y;
        }
        #pragma unroll
        for (int kk = 0; kk < 8; kk++) {
            const float rhA = fmaxf(h[0][kk], 0.0f);
            const float rhB = fmaxf(h[1][kk], 0.0f);
            const u64 a0 = dup2(__shfl_sync(FULL, rhA, 0, 4));
            const u64 a1 = dup2(__shfl_sync(FULL, rhA, 1, 4));
            const u64 a2 = dup2(__shfl_sync(FULL, rhA, 2, 4));
            const u64 a3 = dup2(__shfl_sync(FULL, rhA, 3, 4));
            const u64 c0 = dup2(__shfl_sync(FULL, rhB, 0, 4));
            const u64 c1 = dup2(__shfl_sync(FULL, rhB, 1, 4));
            const u64 c2 = dup2(__shfl_sync(FULL, rhB, 2, 4));
            const u64 c3 = dup2(__shfl_sync(FULL, rhB, 3, 4));

            const ulonglong2* r0 = (const ulonglong2*)(w1base + (kk     ) * 32);
            const ulonglong2* r1 = (const ulonglong2*)(w1base + (kk +  8) * 32);
            const ulonglong2* r2 = (const ulonglong2*)(w1base + (kk + 16) * 32);
            const ulonglong2* r3 = (const ulonglong2*)(w1base + (kk + 24) * 32);
            #pragma unroll
            for (int q = 0; q < 2; q++) {
                const ulonglong2 wa = r0[q], we = r1[q], wf = r2[q], wg = r3[q];
                fma2(accA[2*q], a0, wa.x);  fma2(accA[2*q+1], a0, wa.y);
                fma2(accA[2*q], a1, we.x);  fma2(accA[2*q+1], a1, we.y);
                fma2(accA[2*q], a2, wf.x);  fma2(accA[2*q+1], a2, wf.y);
                fma2(accA[2*q], a3, wg.x);  fma2(accA[2*q+1], a3, wg.y);
                fma2(accB[2*q], c0, wa.x);  fma2(accB[2*q+1], c0, wa.y);
                fma2(accB[2*q], c1, we.x);  fma2(accB[2*q+1], c1, we.y);
                fma2(accB[2*q], c2, wf.x);  fma2(accB[2*q+1], c2, wf.y);
                fma2(accB[2*q], c3, wg.x);  fma2(accB[2*q+1], c3, wg.y);
            }
        }
        #pragma unroll
        for (int m = 0; m < 4; m++) {
            float d0, d1;
            upk2(accA[m], d0, d1); x[0][2*m] += d0; x[0][2*m + 1] += d1;
            upk2(accB[m], d0, d1); x[1][2*m] += d0; x[1][2*m + 1] += d1;
        }
    }

    // ---- output head ----
    #pragma unroll
    for (int pp = 0; pp < 2; pp++) {
        float acc = 0.0f;
        #pragma unroll
        for (int j = 0; j < 8; j++)
            acc = fmaf(fmaxf(x[pp][j], 0.0f), sWo[chb + j], acc);
        acc += __shfl_xor_sync(FULL, acc, 1);
        acc += __shfl_xor_sync(FULL, acc, 2);
        if (q4 == 0) out[pp ? pt1 : pt0] = acc + sbo;
    }
}

extern "C" void kernel_launch(void* const* d_in, const int* in_sizes, int n_in,
                              void* d_out, int out_size)
{
    const float* p    = (const float*)d_in[0];
    // d_in[1] = z (unused by the reference graph)
    const float* c    = (const float*)d_in[2];
    const float* Cm   = (const float*)d_in[3];
    const float* fpW  = (const float*)d_in[4];
    const float* fpb  = (const float*)d_in[5];
    const float* W0   = (const float*)d_in[6];
    const float* b0   = (const float*)d_in[7];
    const float* W1   = (const float*)d_in[8];
    const float* b1   = (const float*)d_in[9];
    const float* Wo   = (const float*)d_in[10];
    const float* bo   = (const float*)d_in[11];
    float* out = (float*)d_out;

    decoder_fused_kernel<<<NPTS / PPB, TPB>>>(p, c, Cm, fpW, fpb, W0, b0, W1, b1, Wo, bo, out);
}

// round 5
// speedup vs baseline: 1.7574x; 1.2872x over previous
#include <cuda_runtime.h>

#define NPTS   65536     // B*T
#define TPB    256
#define PPB    256       // 64 groups x 4 points per thread
#define NBLKS  (NPTS / PPB)

typedef unsigned long long u64;

__device__ __forceinline__ u64 pk2(float a, float b) {
    u64 r; asm("mov.b64 %0, {%1,%2};" : "=l"(r) : "f"(a), "f"(b)); return r;
}
__device__ __forceinline__ u64 dup2(float a) { return pk2(a, a); }
__device__ __forceinline__ void upk2(u64 v, float& a, float& b) {
    asm("mov.b64 {%0,%1}, %2;" : "=f"(a), "=f"(b) : "l"(v));
}
__device__ __forceinline__ void fma2(u64& d, u64 a, u64 b) {
    asm("fma.rn.f32x2 %0, %1, %2, %0;" : "+l"(d) : "l"(a), "l"(b));
}
__device__ __forceinline__ u64 add2(u64 a, u64 b) {
    u64 r; asm("add.rn.f32x2 %0, %1, %2;" : "=l"(r) : "l"(a), "l"(b)); return r;
}

// dynamic smem float-offsets
#define OW0 0          // 5120
#define OW1 5120       // 5120
#define OB0 10240      // 160
#define OB1 10400      // 160
#define OWP 10560      // 96
#define OBP 10656      // 32
#define OWO 10688      // 32
#define OC  10720      // 32  (sC[4][8])
#define OBO 10752      // 1
#define OCF 10768      // cf region: 8 chunks x 256 threads x 16B = 32KB (16B aligned: 10768*4=43072)
#define SMEM_BYTES ((10768 + 8192) * 4)   // 75840 B

// one GEMV stage: acc[pp][t] += sum_k relu(xin_k) * W[k][ch-slice], packed f32x2
__device__ __forceinline__ void gemv_step(u64 acc[4][4], const u64 xin[4][4],
                                          const float* __restrict__ wbase)
{
    const unsigned FULL = 0xffffffffu;
    #pragma unroll
    for (int kk = 0; kk < 8; kk++) {
        const ulonglong2* r0 = (const ulonglong2*)(wbase + (kk     ) * 32);
        const ulonglong2* r1 = (const ulonglong2*)(wbase + (kk +  8) * 32);
        const ulonglong2* r2 = (const ulonglong2*)(wbase + (kk + 16) * 32);
        const ulonglong2* r3 = (const ulonglong2*)(wbase + (kk + 24) * 32);
        const ulonglong2 wa0 = r0[0], wa1 = r0[1];
        const ulonglong2 wb0 = r1[0], wb1 = r1[1];
        const ulonglong2 wc0 = r2[0], wc1 = r2[1];
        const ulonglong2 wd0 = r3[0], wd1 = r3[1];
        #pragma unroll
        for (int pp = 0; pp < 4; pp++) {
            float lo, hi; upk2(xin[pp][kk >> 1], lo, hi);
            const float rx = fmaxf((kk & 1) ? hi : lo, 0.0f);
            const u64 v0 = dup2(__shfl_sync(FULL, rx, 0, 4));
            const u64 v1 = dup2(__shfl_sync(FULL, rx, 1, 4));
            const u64 v2 = dup2(__shfl_sync(FULL, rx, 2, 4));
            const u64 v3 = dup2(__shfl_sync(FULL, rx, 3, 4));
            fma2(acc[pp][0], v0, wa0.x); fma2(acc[pp][1], v0, wa0.y);
            fma2(acc[pp][2], v0, wa1.x); fma2(acc[pp][3], v0, wa1.y);
            fma2(acc[pp][0], v1, wb0.x); fma2(acc[pp][1], v1, wb0.y);
            fma2(acc[pp][2], v1, wb1.x); fma2(acc[pp][3], v1, wb1.y);
            fma2(acc[pp][0], v2, wc0.x); fma2(acc[pp][1], v2, wc0.y);
            fma2(acc[pp][2], v2, wc1.x); fma2(acc[pp][3], v2, wc1.y);
            fma2(acc[pp][0], v3, wd0.x); fma2(acc[pp][1], v3, wd0.y);
            fma2(acc[pp][2], v3, wd1.x); fma2(acc[pp][3], v3, wd1.y);
        }
    }
}

__global__ __launch_bounds__(TPB, 2)
void decoder_fused_kernel(
    const float* __restrict__ p,      // [16,4096,3]
    const float* __restrict__ c,      // [16,4,128,128,32]
    const float* __restrict__ Cmat,   // [16,4,4,3]
    const float* __restrict__ fcpW,   // [3,32]
    const float* __restrict__ fcpb,   // [32]
    const float* __restrict__ W0,     // [5,32,32]
    const float* __restrict__ b0,     // [5,32]
    const float* __restrict__ W1,     // [5,32,32]
    const float* __restrict__ b1,     // [5,32]
    const float* __restrict__ Wout,   // [32,1]
    const float* __restrict__ bout,   // [1]
    float* __restrict__ out)          // [16,4096]
{
    extern __shared__ float sm[];
    ulonglong2* scf = (ulonglong2*)(sm + OCF);

    const int tid = threadIdx.x;
    const int q4  = tid & 3;                      // channel quarter
    const int g   = tid >> 2;                     // group id 0..63
    const int pt0 = blockIdx.x * PPB + g;
    const int b   = pt0 >> 12;                    // PPB divides 4096 -> block stays in one batch
    const int chb = q4 * 8;
    const unsigned FULL = 0xffffffffu;

    // ---- stage weights ----
    for (int i = tid; i < 5120; i += TPB) { sm[OW0 + i] = W0[i]; sm[OW1 + i] = W1[i]; }
    if (tid < 160) { sm[OB0 + tid] = b0[tid]; sm[OB1 + tid] = b1[tid]; }
    if (tid < 96) sm[OWP + tid] = fcpW[tid];
    if (tid < 32) { sm[OBP + tid] = fcpb[tid]; sm[OWO + tid] = Wout[tid]; }
    if (tid == 0) sm[OBO] = bout[0];
    if (tid < 28) {
        int l = tid / 7, k = tid % 7;
        const float* Cb = Cmat + (b * 4 + l) * 12;
        sm[OC + l * 8 + k] = (k < 6) ? Cb[k] : (Cb[9] + 0.05f);
    }
    __syncthreads();

    const float interval = 2.0f / 127.0f;

    u64 x2[4][4];     // packed x, 4 points x 8 channels

    // ---- gather + fc_p per point; cf parked in smem ----
    #pragma unroll 1
    for (int pp = 0; pp < 4; pp++) {
        const int pt = pt0 + pp * 64;
        const float p0 = p[pt * 3 + 0];
        const float p1 = p[pt * 3 + 1];
        const float p2 = p[pt * 3 + 2];
        const float ps0 = p0 / 0.55f;
        const float ps1 = p1 / 0.55f;
        const float ps2 = p2 / 0.55f;

        u64 cf2[4];
        #pragma unroll
        for (int m = 0; m < 4; m++) cf2[m] = 0ull;

        #pragma unroll
        for (int l = 0; l < 4; l++) {
            const float c00 = sm[OC + l*8 + 0], c01 = sm[OC + l*8 + 1], c02 = sm[OC + l*8 + 2];
            const float c10 = sm[OC + l*8 + 3], c11 = sm[OC + l*8 + 4], c12 = sm[OC + l*8 + 5];
            const float den = sm[OC + l*8 + 6];

            float px = (c00 * ps0 + c01 * ps1 + c02 * ps2) / den;
            float py = (c10 * ps0 + c11 * ps1 + c12 * ps2) / den;

            float xg = (px + 1.0f) / interval;
            float yg = (py + 1.0f) / interval;
            xg = (xg >= 127.0f) ? 126.9f : xg;  xg = (xg < 0.0f) ? 0.0f : xg;
            yg = (yg >= 127.0f) ? 126.9f : yg;  yg = (yg < 0.0f) ? 0.0f : yg;

            const float xl = rintf(xg - 0.5f), xr = rintf(xg + 0.5f);
            const float yl = rintf(yg - 0.5f), yh = rintf(yg + 0.5f);
            const int xil = (int)xl, xir = (int)xr;
            const int yil = (int)yl, yih = (int)yh;

            const float dx = xr - xg, dy = yh - yg;
            const u64 W11 = dup2(dx * dy);
            const u64 W12 = dup2((1.0f - dx) * dy);
            const u64 W21 = dup2(dx * (1.0f - dy));
            const u64 W22 = dup2((1.0f - dx) * (1.0f - dy));

            const int base = (b * 4 + l) * 128 * 128;
            const ulonglong2* r11 = (const ulonglong2*)(c + (size_t)(base + xil * 128 + yil) * 32) + q4 * 2;
            const ulonglong2* r12 = (const ulonglong2*)(c + (size_t)(base + xir * 128 + yil) * 32) + q4 * 2;
            const ulonglong2* r21 = (const ulonglong2*)(c + (size_t)(base + xil * 128 + yih) * 32) + q4 * 2;
            const ulonglong2* r22 = (const ulonglong2*)(c + (size_t)(base + xir * 128 + yih) * 32) + q4 * 2;

            #pragma unroll
            for (int q = 0; q < 2; q++) {
                const ulonglong2 a  = r11[q];
                const ulonglong2 e  = r12[q];
                const ulonglong2 f  = r21[q];
                const ulonglong2 gg = r22[q];
                fma2(cf2[2*q    ], W11, a.x);   fma2(cf2[2*q + 1], W11, a.y);
                fma2(cf2[2*q    ], W12, e.x);   fma2(cf2[2*q + 1], W12, e.y);
                fma2(cf2[2*q    ], W21, f.x);   fma2(cf2[2*q + 1], W21, f.y);
                fma2(cf2[2*q    ], W22, gg.x);  fma2(cf2[2*q + 1], W22, gg.y);
            }
        }

        // park cf in smem (own slot, no sync needed)
        scf[(pp * 2 + 0) * TPB + tid] = make_ulonglong2(cf2[0], cf2[1]);
        scf[(pp * 2 + 1) * TPB + tid] = make_ulonglong2(cf2[2], cf2[3]);

        // fc_p (cf added at top of block 0 below)
        #pragma unroll
        for (int m = 0; m < 4; m++) {
            const int j0 = chb + 2*m, j1 = j0 + 1;
            float v0 = sm[OBP + j0];
            v0 = fmaf(p0, sm[OWP + j0], v0);
            v0 = fmaf(p1, sm[OWP + 32 + j0], v0);
            v0 = fmaf(p2, sm[OWP + 64 + j0], v0);
            float v1 = sm[OBP + j1];
            v1 = fmaf(p0, sm[OWP + j1], v1);
            v1 = fmaf(p1, sm[OWP + 32 + j1], v1);
            v1 = fmaf(p2, sm[OWP + 64 + j1], v1);
            x2[pp][m] = pk2(v0, v1);
        }
    }

    // ---- 5 resnet blocks; cf re-added at top of each (incl. blk0 = ref's net+cf) ----
    #pragma unroll 1
    for (int blk = 0; blk < 5; blk++) {
        #pragma unroll
        for (int pp = 0; pp < 4; pp++) {
            const ulonglong2 ca = scf[(pp * 2 + 0) * TPB + tid];
            const ulonglong2 cb = scf[(pp * 2 + 1) * TPB + tid];
            x2[pp][0] = add2(x2[pp][0], ca.x);
            x2[pp][1] = add2(x2[pp][1], ca.y);
            x2[pp][2] = add2(x2[pp][2], cb.x);
            x2[pp][3] = add2(x2[pp][3], cb.y);
        }

        // h = relu(x) @ W0 + b0
        u64 acc[4][4];
        {
            const ulonglong2* bb = (const ulonglong2*)(sm + OB0 + blk * 32 + chb);
            const ulonglong2 b01 = bb[0], b23 = bb[1];
            #pragma unroll
            for (int pp = 0; pp < 4; pp++) {
                acc[pp][0] = b01.x; acc[pp][1] = b01.y;
                acc[pp][2] = b23.x; acc[pp][3] = b23.y;
            }
        }
        gemv_step(acc, x2, sm + OW0 + blk * 1024 + chb);

        // x += b1; x += relu(h) @ W1  (accumulate straight into packed x)
        {
            const ulonglong2* bb = (const ulonglong2*)(sm + OB1 + blk * 32 + chb);
            const ulonglong2 b01 = bb[0], b23 = bb[1];
            #pragma unroll
            for (int pp = 0; pp < 4; pp++) {
                x2[pp][0] = add2(x2[pp][0], b01.x);
                x2[pp][1] = add2(x2[pp][1], b01.y);
                x2[pp][2] = add2(x2[pp][2], b23.x);
                x2[pp][3] = add2(x2[pp][3], b23.y);
            }
        }
        gemv_step(x2, acc, sm + OW1 + blk * 1024 + chb);
    }

    // ---- output head ----
    const float sbo = sm[OBO];
    #pragma unroll
    for (int pp = 0; pp < 4; pp++) {
        float acc = 0.0f;
        #pragma unroll
        for (int m = 0; m < 4; m++) {
            float lo, hi; upk2(x2[pp][m], lo, hi);
            acc = fmaf(fmaxf(lo, 0.0f), sm[OWO + chb + 2*m    ], acc);
            acc = fmaf(fmaxf(hi, 0.0f), sm[OWO + chb + 2*m + 1], acc);
        }
        acc += __shfl_xor_sync(FULL, acc, 1);
        acc += __shfl_xor_sync(FULL, acc, 2);
        if (q4 == 0) out[pt0 + pp * 64] = acc + sbo;
    }
}

extern "C" void kernel_launch(void* const* d_in, const int* in_sizes, int n_in,
                              void* d_out, int out_size)
{
    const float* p    = (const float*)d_in[0];
    // d_in[1] = z (unused by the reference graph)
    const float* c    = (const float*)d_in[2];
    const float* Cm   = (const float*)d_in[3];
    const float* fpW  = (const float*)d_in[4];
    const float* fpb  = (const float*)d_in[5];
    const float* W0   = (const float*)d_in[6];
    const float* b0   = (const float*)d_in[7];
    const float* W1   = (const float*)d_in[8];
    const float* b1   = (const float*)d_in[9];
    const float* Wo   = (const float*)d_in[10];
    const float* bo   = (const float*)d_in[11];
    float* out = (float*)d_out;

    cudaFuncSetAttribute(decoder_fused_kernel,
                         cudaFuncAttributeMaxDynamicSharedMemorySize, SMEM_BYTES);
    decoder_fused_kernel<<<NBLKS, TPB, SMEM_BYTES>>>(p, c, Cm, fpW, fpb, W0, b0, W1, b1, Wo, bo, out);
}